// round 12
// baseline (speedup 1.0000x reference)
#include <cuda_runtime.h>
#include <cuda_fp16.h>

#define NN   100000
#define EE   3200000
#define KORD 10
#define CC   64
#define FIN  512

// ---------------- scratch (static __device__, per allocation rules) -------------
__device__ int     d_deg[NN];
__device__ int     d_rowptr[NN + 1];
__device__ int     d_cursor[NN];
__device__ int     d_blk[128];
__device__ float   d_dinv[NN];            // deg>0 ? rsqrt(deg) : 1
__device__ float   d_wi[NN];              // dinv^2
__device__ float   d_sdeg[NN];            // 1/dinv  (sqrt(deg) or 1)
__device__ int     d_srcs[EE];
__device__ __half2 d_Ph[3][NN * (CC / 2)];  // rotating Chebyshev buffers, R_n = dinv*P_n (fp16)
__device__ float   d_acc[NN * CC];          // weighted combine accumulator (fp32)

// ---------------- CSR build ----------------------------------------------------
__global__ void k_zero_deg() {
    int i = blockIdx.x * blockDim.x + threadIdx.x;
    if (i < NN) d_deg[i] = 0;
}

__global__ void k_count(const int* __restrict__ ei) {
    int e = blockIdx.x * blockDim.x + threadIdx.x;
    if (e < EE) atomicAdd(&d_deg[ei[EE + e]], 1);
}

__global__ void k_scan1() {
    __shared__ int sh[1024];
    int i = blockIdx.x * 1024 + threadIdx.x;
    int v = (i < NN) ? d_deg[i] : 0;
    sh[threadIdx.x] = v;
    __syncthreads();
    for (int off = 1; off < 1024; off <<= 1) {
        int t = (threadIdx.x >= off) ? sh[threadIdx.x - off] : 0;
        __syncthreads();
        sh[threadIdx.x] += t;
        __syncthreads();
    }
    if (i < NN) d_rowptr[i] = sh[threadIdx.x] - v;     // block-local exclusive
    if (threadIdx.x == 1023) d_blk[blockIdx.x] = sh[1023];
}

__global__ void k_scan2(int nblk) {                    // parallel exclusive scan, nblk<=128
    __shared__ int sh[128];
    int t = threadIdx.x;
    int v = (t < nblk) ? d_blk[t] : 0;
    sh[t] = v;
    __syncthreads();
    for (int off = 1; off < 128; off <<= 1) {
        int u = (t >= off) ? sh[t - off] : 0;
        __syncthreads();
        sh[t] += u;
        __syncthreads();
    }
    if (t < nblk) d_blk[t] = sh[t] - v;
}

__global__ void k_scan3() {
    int i = blockIdx.x * blockDim.x + threadIdx.x;
    if (i < NN) {
        int rp = d_rowptr[i] + d_blk[i >> 10];
        d_rowptr[i] = rp;
        d_cursor[i] = rp;
        int dg = d_deg[i];
        d_dinv[i] = (dg > 0) ? rsqrtf((float)dg) : 1.0f;
        d_wi[i]   = (dg > 0) ? (1.0f / (float)dg) : 1.0f;
        d_sdeg[i] = (dg > 0) ? sqrtf((float)dg) : 1.0f;
    }
    if (i == 0) d_rowptr[NN] = EE;
}

__global__ void k_scatter(const int* __restrict__ ei) {
    int e = blockIdx.x * blockDim.x + threadIdx.x;
    if (e < EE) {
        int r = ei[e];
        int c = ei[EE + e];
        int p = atomicAdd(&d_cursor[c], 1);
        d_srcs[p] = r;
    }
}

// ---------------- packed f32x2 FMA ---------------------------------------------
__device__ __forceinline__ unsigned long long ffma2(unsigned long long a,
                                                    unsigned long long b,
                                                    unsigned long long c) {
    unsigned long long d;
    asm("fma.rn.f32x2 %0, %1, %2, %3;" : "=l"(d) : "l"(a), "l"(b), "l"(c));
    return d;
}
__device__ __forceinline__ float2 u2f2(unsigned long long v) {
    float2 f;
    asm("mov.b64 {%0, %1}, %2;" : "=f"(f.x), "=f"(f.y) : "l"(v));
    return f;
}

// ---------------- GEMM: h = x @ W + b  (FFMA2), fused R0/acc init ----------------
// 64x64 tile, 256 threads, 4x4 microtile (pairs over M), K-tile 32.
__global__ __launch_bounds__(256) void k_gemm(const float* __restrict__ x,
                                              const float* __restrict__ W,
                                              const float* __restrict__ bias,
                                              const float* __restrict__ mfw) {
    __shared__ float  xsT[32][68];     // [k][m], padded (272 B row = 16B-aligned)
    __shared__ float2 Ws2[32][64];     // [k][c] duplicated pairs (w,w)
    int tid = threadIdx.x;
    int m0  = blockIdx.x * 64;
    int ty  = tid >> 4, tx = tid & 15;

    unsigned long long acc[2][4];      // [m-pair][col], each holds rows (2p, 2p+1)
#pragma unroll
    for (int i = 0; i < 2; i++)
#pragma unroll
        for (int j = 0; j < 4; j++) acc[i][j] = 0ull;

    for (int k0 = 0; k0 < FIN; k0 += 32) {
#pragma unroll
        for (int it = 0; it < 2; ++it) {
            int idx = tid + it * 256;
            int row = idx >> 3, fc = idx & 7;
            float4 v = make_float4(0.f, 0.f, 0.f, 0.f);
            int gr = m0 + row;
            if (gr < NN) v = *(const float4*)(x + (long)gr * FIN + k0 + fc * 4);
            xsT[fc * 4 + 0][row] = v.x;
            xsT[fc * 4 + 1][row] = v.y;
            xsT[fc * 4 + 2][row] = v.z;
            xsT[fc * 4 + 3][row] = v.w;
        }
#pragma unroll
        for (int it = 0; it < 2; ++it) {
            int idx = tid + it * 256;
            int kr = idx >> 4, fc = idx & 15;
            float4 v = *(const float4*)(W + (k0 + kr) * CC + fc * 4);
            Ws2[kr][fc * 4 + 0] = make_float2(v.x, v.x);
            Ws2[kr][fc * 4 + 1] = make_float2(v.y, v.y);
            Ws2[kr][fc * 4 + 2] = make_float2(v.z, v.z);
            Ws2[kr][fc * 4 + 3] = make_float2(v.w, v.w);
        }
        __syncthreads();
#pragma unroll
        for (int kk = 0; kk < 32; ++kk) {
            ulonglong2 av  = *(const ulonglong2*)&xsT[kk][ty * 4];      // rows (0,1),(2,3)
            ulonglong2 w01 = *(const ulonglong2*)&Ws2[kk][tx * 4];      // cols 0,1 dup pairs
            ulonglong2 w23 = *(const ulonglong2*)&Ws2[kk][tx * 4 + 2];  // cols 2,3 dup pairs
            acc[0][0] = ffma2(av.x, w01.x, acc[0][0]);
            acc[0][1] = ffma2(av.x, w01.y, acc[0][1]);
            acc[0][2] = ffma2(av.x, w23.x, acc[0][2]);
            acc[0][3] = ffma2(av.x, w23.y, acc[0][3]);
            acc[1][0] = ffma2(av.y, w01.x, acc[1][0]);
            acc[1][1] = ffma2(av.y, w01.y, acc[1][1]);
            acc[1][2] = ffma2(av.y, w23.x, acc[1][2]);
            acc[1][3] = ffma2(av.y, w23.y, acc[1][3]);
        }
        __syncthreads();
    }

    // unpack: hv[row 0..3][col 0..3]
    float hv[4][4];
#pragma unroll
    for (int j = 0; j < 4; j++) {
        float2 p = u2f2(acc[0][j]);
        float2 q = u2f2(acc[1][j]);
        hv[0][j] = p.x; hv[1][j] = p.y; hv[2][j] = q.x; hv[3][j] = q.y;
    }

    float4 b4 = *(const float4*)(bias + tx * 4);
    float4 w0 = *(const float4*)(mfw + tx * 4);   // mf_weights[0][c], coef0 = 1
#pragma unroll
    for (int i = 0; i < 4; i++) {
        int row = m0 + ty * 4 + i;
        if (row < NN) {
            float h0 = hv[i][0] + b4.x;
            float h1 = hv[i][1] + b4.y;
            float h2 = hv[i][2] + b4.z;
            float h3 = hv[i][3] + b4.w;
            float dv = d_dinv[row];
            __half2* dst = d_Ph[0] + (long)row * (CC / 2) + tx * 2;
            dst[0] = __floats2half2_rn(dv * h0, dv * h1);   // R0 = dinv * h
            dst[1] = __floats2half2_rn(dv * h2, dv * h3);
            *(float4*)(&d_acc[(long)row * CC + tx * 4]) =
                make_float4(h0 * w0.x, h1 * w0.y, h2 * w0.z, h3 * w0.w);
        }
    }
}

// ---------------- fused propagate + recurrence + weighted accumulate ------------
// Folded norms: R_n = dinv*P_n stored fp16. s = sum_src R_{n-1}[src].
//   n==1: R_1 = w_i*s        (w_i = dinv^2)
//   n>=2: R_n = 2*w_i*s - R_{n-2}
//   P_n  = sdeg_i * R_n;  acc += lap[n-1]*mfw[n][c]*P_n
// Final iteration: fused log_softmax straight to out, no stores.
__global__ __launch_bounds__(256) void k_prop(int n, int inb, int outb, int pb,
                                              const float* __restrict__ lap,
                                              const float* __restrict__ mfw,
                                              float* __restrict__ out) {
    int gw   = (blockIdx.x * blockDim.x + threadIdx.x) >> 5;
    int lane = threadIdx.x & 31;
    if (gw >= NN) return;
    const __half2* __restrict__ Pin = d_Ph[inb];
    int beg = d_rowptr[gw], end = d_rowptr[gw + 1];

    float sx = 0.f, sy = 0.f;
    int p = beg;
    for (; p + 4 <= end; p += 4) {
        int s0 = d_srcs[p], s1 = d_srcs[p + 1], s2 = d_srcs[p + 2], s3 = d_srcs[p + 3];
        float2 f0 = __half22float2(Pin[(long)s0 * (CC / 2) + lane]);
        float2 f1 = __half22float2(Pin[(long)s1 * (CC / 2) + lane]);
        float2 f2 = __half22float2(Pin[(long)s2 * (CC / 2) + lane]);
        float2 f3 = __half22float2(Pin[(long)s3 * (CC / 2) + lane]);
        sx += f0.x + f1.x + f2.x + f3.x;
        sy += f0.y + f1.y + f2.y + f3.y;
    }
    for (; p < end; ++p) {
        float2 f = __half22float2(Pin[(long)d_srcs[p] * (CC / 2) + lane]);
        sx += f.x;
        sy += f.y;
    }

    float w = d_wi[gw];
    float px, py;
    if (n >= 2) {
        float2 q = __half22float2(d_Ph[pb][(long)gw * (CC / 2) + lane]);
        px = 2.f * w * sx - q.x;
        py = 2.f * w * sy - q.y;
    } else {
        px = w * sx;
        py = w * sy;
    }

    int c2 = 2 * lane;
    float sd   = d_sdeg[gw];
    float coef = lap[n - 1];
    float w0 = coef * mfw[n * CC + c2];
    float w1 = coef * mfw[n * CC + c2 + 1];
    float2 a = *(const float2*)(d_acc + (long)gw * CC + c2);
    a.x += w0 * (sd * px);
    a.y += w1 * (sd * py);

    if (n < KORD) {
        d_Ph[outb][(long)gw * (CC / 2) + lane] = __floats2half2_rn(px, py);
        *(float2*)(d_acc + (long)gw * CC + c2) = a;
    } else {
        // fused log_softmax over the warp-held 64-wide row
        float m = fmaxf(a.x, a.y);
#pragma unroll
        for (int o = 16; o; o >>= 1) m = fmaxf(m, __shfl_xor_sync(0xffffffffu, m, o));
        float s = expf(a.x - m) + expf(a.y - m);
#pragma unroll
        for (int o = 16; o; o >>= 1) s += __shfl_xor_sync(0xffffffffu, s, o);
        float l = m + logf(s);
        *(float2*)(out + (long)gw * CC + c2) = make_float2(a.x - l, a.y - l);
    }
}

// ---------------- launch --------------------------------------------------------
extern "C" void kernel_launch(void* const* d_in, const int* in_sizes, int n_in,
                              void* d_out, int out_size) {
    const float* x   = (const float*)d_in[0];
    const int*   ei  = (const int*)d_in[1];     // int32 (JAX default x64-disabled)
    const float* W   = (const float*)d_in[2];
    const float* b   = (const float*)d_in[3];
    const float* lap = (const float*)d_in[4];
    const float* mfw = (const float*)d_in[5];
    float*       out = (float*)d_out;

    (void)in_sizes; (void)n_in; (void)out_size;

    k_zero_deg<<<(NN + 255) / 256, 256>>>();
    k_count<<<(EE + 255) / 256, 256>>>(ei);
    int nblk = (NN + 1023) / 1024;   // 98
    k_scan1<<<nblk, 1024>>>();
    k_scan2<<<1, 128>>>(nblk);
    k_scan3<<<(NN + 255) / 256, 256>>>();
    k_scatter<<<(EE + 255) / 256, 256>>>(ei);

    k_gemm<<<(NN + 63) / 64, 256>>>(x, W, b, mfw);

    // warps = NN, 8 warps/block
    int prop_blocks = (NN + 7) / 8;
    for (int n = 1; n <= KORD; n++) {
        int inb  = (n - 1) % 3;
        int outb = n % 3;
        int pb   = (n + 1) % 3;   // == (n-2) mod 3
        k_prop<<<prop_blocks, 256>>>(n, inb, outb, pb, lap, mfw, out);
    }
}

// round 13
// speedup vs baseline: 1.3170x; 1.3170x over previous
#include <cuda_runtime.h>
#include <cuda_fp16.h>

#define NN   100000
#define EE   3200000
#define KORD 10
#define CC   64
#define FIN  512

// ---------------- scratch (static __device__, per allocation rules) -------------
// d_deg is zero at module load; k_scan3 re-zeroes it after use so every
// kernel_launch call sees it zeroed (invariant maintained across graph replays).
__device__ int     d_deg[NN];
__device__ int     d_rowptr[NN + 1];
__device__ int     d_cursor[NN];
__device__ int     d_blk[128];
__device__ float   d_dinv[NN];              // deg>0 ? rsqrt(deg) : 1
__device__ float   d_wi[NN];                // dinv^2
__device__ float   d_sdeg[NN];              // sqrt(deg) or 1
__device__ int     d_srcs[EE];
__device__ __half2 d_Ph[3][NN * (CC / 2)];  // rotating Chebyshev buffers, R_n = dinv*P_n
__device__ float   d_acc[NN * CC];          // weighted combine accumulator (fp32)

// ---------------- CSR build ----------------------------------------------------
__global__ void k_count(const int* __restrict__ ei) {
    int e = blockIdx.x * blockDim.x + threadIdx.x;
    if (e < EE) atomicAdd(&d_deg[ei[EE + e]], 1);
}

__global__ void k_scan1() {
    __shared__ int sh[1024];
    int i = blockIdx.x * 1024 + threadIdx.x;
    int v = (i < NN) ? d_deg[i] : 0;
    sh[threadIdx.x] = v;
    __syncthreads();
    for (int off = 1; off < 1024; off <<= 1) {
        int t = (threadIdx.x >= off) ? sh[threadIdx.x - off] : 0;
        __syncthreads();
        sh[threadIdx.x] += t;
        __syncthreads();
    }
    if (i < NN) d_rowptr[i] = sh[threadIdx.x] - v;     // block-local exclusive
    if (threadIdx.x == 1023) d_blk[blockIdx.x] = sh[1023];
}

__global__ void k_scan2(int nblk) {                    // parallel exclusive scan, nblk<=128
    __shared__ int sh[128];
    int t = threadIdx.x;
    int v = (t < nblk) ? d_blk[t] : 0;
    sh[t] = v;
    __syncthreads();
    for (int off = 1; off < 128; off <<= 1) {
        int u = (t >= off) ? sh[t - off] : 0;
        __syncthreads();
        sh[t] += u;
        __syncthreads();
    }
    if (t < nblk) d_blk[t] = sh[t] - v;
}

__global__ void k_scan3() {
    int i = blockIdx.x * blockDim.x + threadIdx.x;
    if (i < NN) {
        int rp = d_rowptr[i] + d_blk[i >> 10];
        d_rowptr[i] = rp;
        d_cursor[i] = rp;
        int dg = d_deg[i];
        d_deg[i] = 0;                       // restore invariant for next launch
        d_dinv[i] = (dg > 0) ? rsqrtf((float)dg) : 1.0f;
        d_wi[i]   = (dg > 0) ? (1.0f / (float)dg) : 1.0f;
        d_sdeg[i] = (dg > 0) ? sqrtf((float)dg) : 1.0f;
    }
    if (i == 0) d_rowptr[NN] = EE;
}

__global__ void k_scatter(const int* __restrict__ ei) {
    int e = blockIdx.x * blockDim.x + threadIdx.x;
    if (e < EE) {
        int r = ei[e];
        int c = ei[EE + e];
        int p = atomicAdd(&d_cursor[c], 1);
        d_srcs[p] = r;
    }
}

// ---------------- GEMM: h = x @ W + b (fp32 float4, R11 version) ----------------
// 64x64 tile, 256 threads, 4x4 microtile, K-tile 32. Epilogue writes fp16 R0
// (= dinv*h) and initializes acc with coef0=1 * mfw[0].
__global__ __launch_bounds__(256) void k_gemm(const float* __restrict__ x,
                                              const float* __restrict__ W,
                                              const float* __restrict__ bias,
                                              const float* __restrict__ mfw) {
    __shared__ float xsT[32][68];   // [k][m], padded
    __shared__ float Ws[32][64];    // [k][c]
    int tid = threadIdx.x;
    int m0  = blockIdx.x * 64;
    int ty  = tid >> 4, tx = tid & 15;

    float acc[4][4];
#pragma unroll
    for (int i = 0; i < 4; i++)
#pragma unroll
        for (int j = 0; j < 4; j++) acc[i][j] = 0.f;

    for (int k0 = 0; k0 < FIN; k0 += 32) {
#pragma unroll
        for (int it = 0; it < 2; ++it) {
            int idx = tid + it * 256;
            int row = idx >> 3, fc = idx & 7;
            float4 v = make_float4(0.f, 0.f, 0.f, 0.f);
            int gr = m0 + row;
            if (gr < NN) v = *(const float4*)(x + (long)gr * FIN + k0 + fc * 4);
            xsT[fc * 4 + 0][row] = v.x;
            xsT[fc * 4 + 1][row] = v.y;
            xsT[fc * 4 + 2][row] = v.z;
            xsT[fc * 4 + 3][row] = v.w;
        }
#pragma unroll
        for (int it = 0; it < 2; ++it) {
            int idx = tid + it * 256;
            int kr = idx >> 4, fc = idx & 15;
            *(float4*)&Ws[kr][fc * 4] = *(const float4*)(W + (k0 + kr) * CC + fc * 4);
        }
        __syncthreads();
#pragma unroll
        for (int kk = 0; kk < 32; ++kk) {
            float4 a  = *(const float4*)&xsT[kk][ty * 4];
            float4 bb = *(const float4*)&Ws[kk][tx * 4];
            acc[0][0] += a.x * bb.x; acc[0][1] += a.x * bb.y; acc[0][2] += a.x * bb.z; acc[0][3] += a.x * bb.w;
            acc[1][0] += a.y * bb.x; acc[1][1] += a.y * bb.y; acc[1][2] += a.y * bb.z; acc[1][3] += a.y * bb.w;
            acc[2][0] += a.z * bb.x; acc[2][1] += a.z * bb.y; acc[2][2] += a.z * bb.z; acc[2][3] += a.z * bb.w;
            acc[3][0] += a.w * bb.x; acc[3][1] += a.w * bb.y; acc[3][2] += a.w * bb.z; acc[3][3] += a.w * bb.w;
        }
        __syncthreads();
    }

    float4 b4 = *(const float4*)(bias + tx * 4);
    float4 w0 = *(const float4*)(mfw + tx * 4);   // mf_weights[0][c], coef0 = 1
#pragma unroll
    for (int i = 0; i < 4; i++) {
        int row = m0 + ty * 4 + i;
        if (row < NN) {
            float h0 = acc[i][0] + b4.x;
            float h1 = acc[i][1] + b4.y;
            float h2 = acc[i][2] + b4.z;
            float h3 = acc[i][3] + b4.w;
            float dv = d_dinv[row];
            __half2* dst = d_Ph[0] + (long)row * (CC / 2) + tx * 2;
            dst[0] = __floats2half2_rn(dv * h0, dv * h1);   // R0 = dinv * h
            dst[1] = __floats2half2_rn(dv * h2, dv * h3);
            *(float4*)(&d_acc[(long)row * CC + tx * 4]) =
                make_float4(h0 * w0.x, h1 * w0.y, h2 * w0.z, h3 * w0.w);
        }
    }
}

// ---------------- fused propagate + recurrence + weighted accumulate ------------
// Folded norms: R_n = dinv*P_n stored fp16. s = sum_src R_{n-1}[src].
//   n==1: R_1 = w_i*s        (w_i = dinv^2)
//   n>=2: R_n = 2*w_i*s - R_{n-2}
//   P_n  = sdeg_i * R_n;  acc += lap[n-1]*mfw[n][c]*P_n
// Final iteration: fused log_softmax straight to out, no stores.
__global__ __launch_bounds__(256) void k_prop(int n, int inb, int outb, int pb,
                                              const float* __restrict__ lap,
                                              const float* __restrict__ mfw,
                                              float* __restrict__ out) {
    int gw   = (blockIdx.x * blockDim.x + threadIdx.x) >> 5;
    int lane = threadIdx.x & 31;
    if (gw >= NN) return;
    const __half2* __restrict__ Pin = d_Ph[inb];
    int beg = d_rowptr[gw], end = d_rowptr[gw + 1];

    float sx = 0.f, sy = 0.f;
    int p = beg;
    for (; p + 4 <= end; p += 4) {
        int s0 = d_srcs[p], s1 = d_srcs[p + 1], s2 = d_srcs[p + 2], s3 = d_srcs[p + 3];
        float2 f0 = __half22float2(Pin[(long)s0 * (CC / 2) + lane]);
        float2 f1 = __half22float2(Pin[(long)s1 * (CC / 2) + lane]);
        float2 f2 = __half22float2(Pin[(long)s2 * (CC / 2) + lane]);
        float2 f3 = __half22float2(Pin[(long)s3 * (CC / 2) + lane]);
        sx += f0.x + f1.x + f2.x + f3.x;
        sy += f0.y + f1.y + f2.y + f3.y;
    }
    for (; p < end; ++p) {
        float2 f = __half22float2(Pin[(long)d_srcs[p] * (CC / 2) + lane]);
        sx += f.x;
        sy += f.y;
    }

    float w = d_wi[gw];
    float px, py;
    if (n >= 2) {
        float2 q = __half22float2(d_Ph[pb][(long)gw * (CC / 2) + lane]);
        px = 2.f * w * sx - q.x;
        py = 2.f * w * sy - q.y;
    } else {
        px = w * sx;
        py = w * sy;
    }

    int c2 = 2 * lane;
    float sd   = d_sdeg[gw];
    float coef = lap[n - 1];
    float w0 = coef * mfw[n * CC + c2];
    float w1 = coef * mfw[n * CC + c2 + 1];
    float2 a = *(const float2*)(d_acc + (long)gw * CC + c2);
    a.x += w0 * (sd * px);
    a.y += w1 * (sd * py);

    if (n < KORD) {
        d_Ph[outb][(long)gw * (CC / 2) + lane] = __floats2half2_rn(px, py);
        *(float2*)(d_acc + (long)gw * CC + c2) = a;
    } else {
        // fused log_softmax over the warp-held 64-wide row
        float m = fmaxf(a.x, a.y);
#pragma unroll
        for (int o = 16; o; o >>= 1) m = fmaxf(m, __shfl_xor_sync(0xffffffffu, m, o));
        float s = expf(a.x - m) + expf(a.y - m);
#pragma unroll
        for (int o = 16; o; o >>= 1) s += __shfl_xor_sync(0xffffffffu, s, o);
        float l = m + logf(s);
        *(float2*)(out + (long)gw * CC + c2) = make_float2(a.x - l, a.y - l);
    }
}

// ---------------- launch --------------------------------------------------------
extern "C" void kernel_launch(void* const* d_in, const int* in_sizes, int n_in,
                              void* d_out, int out_size) {
    const float* x   = (const float*)d_in[0];
    const int*   ei  = (const int*)d_in[1];     // int32 (JAX default x64-disabled)
    const float* W   = (const float*)d_in[2];
    const float* b   = (const float*)d_in[3];
    const float* lap = (const float*)d_in[4];
    const float* mfw = (const float*)d_in[5];
    float*       out = (float*)d_out;

    (void)in_sizes; (void)n_in; (void)out_size;

    // d_deg is zeroed (module load on call 1; k_scan3 re-zeroes every call)
    k_count<<<(EE + 255) / 256, 256>>>(ei);          // launch 1
    int nblk = (NN + 1023) / 1024;                   // 98
    k_scan1<<<nblk, 1024>>>();                       // launch 2
    k_scan2<<<1, 128>>>(nblk);                       // launch 3
    k_scan3<<<(NN + 255) / 256, 256>>>();            // launch 4
    k_scatter<<<(EE + 255) / 256, 256>>>(ei);        // launch 5

    k_gemm<<<(NN + 63) / 64, 256>>>(x, W, b, mfw);   // launch 6  (ncu -s 5 -c 1 target)

    // warps = NN, 8 warps/block
    int prop_blocks = (NN + 7) / 8;
    for (int n = 1; n <= KORD; n++) {
        int inb  = (n - 1) % 3;
        int outb = n % 3;
        int pb   = (n + 1) % 3;   // == (n-2) mod 3
        k_prop<<<prop_blocks, 256>>>(n, inb, outb, pb, lap, mfw, out);
    }
}

// round 14
// speedup vs baseline: 1.3202x; 1.0024x over previous
#include <cuda_runtime.h>
#include <cuda_fp16.h>

#define NN   100000
#define EE   3200000
#define KORD 10
#define CC   64
#define FIN  512

// ---------------- scratch (static __device__, per allocation rules) -------------
// d_deg is zero at module load; k_scan3 re-zeroes it after use so every
// kernel_launch call sees it zeroed (invariant maintained across graph replays).
__device__ int     d_deg[NN];
__device__ int     d_rowptr[NN + 1];
__device__ int     d_cursor[NN];
__device__ int     d_blk[128];
__device__ float   d_dinv[NN];              // deg>0 ? rsqrt(deg) : 1
__device__ float   d_wi[NN];                // dinv^2
__device__ float   d_sdeg[NN];              // sqrt(deg) or 1
__device__ int     d_srcs[EE];
__device__ __half2 d_Ph[3][NN * (CC / 2)];  // rotating Chebyshev buffers, R_n = dinv*P_n
__device__ float   d_acc[NN * CC];          // weighted combine accumulator (fp32)

// ---------------- CSR build ----------------------------------------------------
__global__ void k_count(const int* __restrict__ ei) {
    int e = blockIdx.x * blockDim.x + threadIdx.x;
    if (e < EE) atomicAdd(&d_deg[ei[EE + e]], 1);
}

__global__ void k_scan1() {
    __shared__ int sh[1024];
    int i = blockIdx.x * 1024 + threadIdx.x;
    int v = (i < NN) ? d_deg[i] : 0;
    sh[threadIdx.x] = v;
    __syncthreads();
    for (int off = 1; off < 1024; off <<= 1) {
        int t = (threadIdx.x >= off) ? sh[threadIdx.x - off] : 0;
        __syncthreads();
        sh[threadIdx.x] += t;
        __syncthreads();
    }
    if (i < NN) d_rowptr[i] = sh[threadIdx.x] - v;     // block-local exclusive
    if (threadIdx.x == 1023) d_blk[blockIdx.x] = sh[1023];
}

__global__ void k_scan2(int nblk) {                    // parallel exclusive scan, nblk<=128
    __shared__ int sh[128];
    int t = threadIdx.x;
    int v = (t < nblk) ? d_blk[t] : 0;
    sh[t] = v;
    __syncthreads();
    for (int off = 1; off < 128; off <<= 1) {
        int u = (t >= off) ? sh[t - off] : 0;
        __syncthreads();
        sh[t] += u;
        __syncthreads();
    }
    if (t < nblk) d_blk[t] = sh[t] - v;
}

__global__ void k_scan3() {
    int i = blockIdx.x * blockDim.x + threadIdx.x;
    if (i < NN) {
        int rp = d_rowptr[i] + d_blk[i >> 10];
        d_rowptr[i] = rp;
        d_cursor[i] = rp;
        int dg = d_deg[i];
        d_deg[i] = 0;                       // restore invariant for next launch
        d_dinv[i] = (dg > 0) ? rsqrtf((float)dg) : 1.0f;
        d_wi[i]   = (dg > 0) ? (1.0f / (float)dg) : 1.0f;
        d_sdeg[i] = (dg > 0) ? sqrtf((float)dg) : 1.0f;
    }
    if (i == 0) d_rowptr[NN] = EE;
}

__global__ void k_scatter(const int* __restrict__ ei) {
    int e = blockIdx.x * blockDim.x + threadIdx.x;
    if (e < EE) {
        int r = ei[e];
        int c = ei[EE + e];
        int p = atomicAdd(&d_cursor[c], 1);
        d_srcs[p] = r;
    }
}

// ---------------- GEMM: h = x @ W + b (fp32 float4, 128x64 tile, 8x4 micro) -----
// 256 threads as 16x16; each thread computes 8 rows x 4 cols. K-tile 32.
// Epilogue writes fp16 R0 (= dinv*h) and initializes acc with coef0=1 * mfw[0].
__global__ __launch_bounds__(256) void k_gemm(const float* __restrict__ x,
                                              const float* __restrict__ W,
                                              const float* __restrict__ bias,
                                              const float* __restrict__ mfw) {
    __shared__ float xsT[32][132];  // [k][m], padded
    __shared__ float Ws[32][64];    // [k][c]
    int tid = threadIdx.x;
    int m0  = blockIdx.x * 128;
    int ty  = tid >> 4, tx = tid & 15;

    float acc[8][4];
#pragma unroll
    for (int i = 0; i < 8; i++)
#pragma unroll
        for (int j = 0; j < 4; j++) acc[i][j] = 0.f;

    for (int k0 = 0; k0 < FIN; k0 += 32) {
        // load x tile: 128 rows x 32 k = 1024 float4s, 4 per thread
#pragma unroll
        for (int it = 0; it < 4; ++it) {
            int idx = tid + it * 256;
            int row = idx >> 3, fc = idx & 7;
            float4 v = make_float4(0.f, 0.f, 0.f, 0.f);
            int gr = m0 + row;
            if (gr < NN) v = *(const float4*)(x + (long)gr * FIN + k0 + fc * 4);
            xsT[fc * 4 + 0][row] = v.x;
            xsT[fc * 4 + 1][row] = v.y;
            xsT[fc * 4 + 2][row] = v.z;
            xsT[fc * 4 + 3][row] = v.w;
        }
        // load W tile: 32 k x 64 c = 512 float4s, 2 per thread
#pragma unroll
        for (int it = 0; it < 2; ++it) {
            int idx = tid + it * 256;
            int kr = idx >> 4, fc = idx & 15;
            *(float4*)&Ws[kr][fc * 4] = *(const float4*)(W + (k0 + kr) * CC + fc * 4);
        }
        __syncthreads();
#pragma unroll
        for (int kk = 0; kk < 32; ++kk) {
            float4 a0 = *(const float4*)&xsT[kk][ty * 8];
            float4 a1 = *(const float4*)&xsT[kk][ty * 8 + 4];
            float4 bb = *(const float4*)&Ws[kk][tx * 4];
            acc[0][0] += a0.x * bb.x; acc[0][1] += a0.x * bb.y; acc[0][2] += a0.x * bb.z; acc[0][3] += a0.x * bb.w;
            acc[1][0] += a0.y * bb.x; acc[1][1] += a0.y * bb.y; acc[1][2] += a0.y * bb.z; acc[1][3] += a0.y * bb.w;
            acc[2][0] += a0.z * bb.x; acc[2][1] += a0.z * bb.y; acc[2][2] += a0.z * bb.z; acc[2][3] += a0.z * bb.w;
            acc[3][0] += a0.w * bb.x; acc[3][1] += a0.w * bb.y; acc[3][2] += a0.w * bb.z; acc[3][3] += a0.w * bb.w;
            acc[4][0] += a1.x * bb.x; acc[4][1] += a1.x * bb.y; acc[4][2] += a1.x * bb.z; acc[4][3] += a1.x * bb.w;
            acc[5][0] += a1.y * bb.x; acc[5][1] += a1.y * bb.y; acc[5][2] += a1.y * bb.z; acc[5][3] += a1.y * bb.w;
            acc[6][0] += a1.z * bb.x; acc[6][1] += a1.z * bb.y; acc[6][2] += a1.z * bb.z; acc[6][3] += a1.z * bb.w;
            acc[7][0] += a1.w * bb.x; acc[7][1] += a1.w * bb.y; acc[7][2] += a1.w * bb.z; acc[7][3] += a1.w * bb.w;
        }
        __syncthreads();
    }

    float4 b4 = *(const float4*)(bias + tx * 4);
    float4 w0 = *(const float4*)(mfw + tx * 4);   // mf_weights[0][c], coef0 = 1
#pragma unroll
    for (int i = 0; i < 8; i++) {
        int row = m0 + ty * 8 + i;
        if (row < NN) {
            float h0 = acc[i][0] + b4.x;
            float h1 = acc[i][1] + b4.y;
            float h2 = acc[i][2] + b4.z;
            float h3 = acc[i][3] + b4.w;
            float dv = d_dinv[row];
            __half2* dst = d_Ph[0] + (long)row * (CC / 2) + tx * 2;
            dst[0] = __floats2half2_rn(dv * h0, dv * h1);   // R0 = dinv * h
            dst[1] = __floats2half2_rn(dv * h2, dv * h3);
            *(float4*)(&d_acc[(long)row * CC + tx * 4]) =
                make_float4(h0 * w0.x, h1 * w0.y, h2 * w0.z, h3 * w0.w);
        }
    }
}

// ---------------- fused propagate + recurrence + weighted accumulate ------------
// Folded norms: R_n = dinv*P_n stored fp16. s = sum_src R_{n-1}[src].
//   n==1: R_1 = w_i*s        (w_i = dinv^2)
//   n>=2: R_n = 2*w_i*s - R_{n-2}
//   P_n  = sdeg_i * R_n;  acc += lap[n-1]*mfw[n][c]*P_n
// Index stream read as aligned int4 (LDG.128 broadcast: 1 issue per 4 edges).
// Final iteration: fused log_softmax straight to out, no stores.
__global__ __launch_bounds__(256) void k_prop(int n, int inb, int outb, int pb,
                                              const float* __restrict__ lap,
                                              const float* __restrict__ mfw,
                                              float* __restrict__ out) {
    int gw   = (blockIdx.x * blockDim.x + threadIdx.x) >> 5;
    int lane = threadIdx.x & 31;
    if (gw >= NN) return;
    const __half2* __restrict__ Pin = d_Ph[inb];
    int beg = d_rowptr[gw], end = d_rowptr[gw + 1];

    float sx = 0.f, sy = 0.f;
    int p = beg;
    // peel to 16B alignment of &d_srcs[p]
    for (; p < end && (p & 3); ++p) {
        float2 f = __half22float2(Pin[(long)d_srcs[p] * (CC / 2) + lane]);
        sx += f.x;
        sy += f.y;
    }
    for (; p + 4 <= end; p += 4) {
        int4 s4 = *(const int4*)&d_srcs[p];          // aligned LDG.128, broadcast
        float2 f0 = __half22float2(Pin[(long)s4.x * (CC / 2) + lane]);
        float2 f1 = __half22float2(Pin[(long)s4.y * (CC / 2) + lane]);
        float2 f2 = __half22float2(Pin[(long)s4.z * (CC / 2) + lane]);
        float2 f3 = __half22float2(Pin[(long)s4.w * (CC / 2) + lane]);
        sx += f0.x + f1.x + f2.x + f3.x;
        sy += f0.y + f1.y + f2.y + f3.y;
    }
    for (; p < end; ++p) {
        float2 f = __half22float2(Pin[(long)d_srcs[p] * (CC / 2) + lane]);
        sx += f.x;
        sy += f.y;
    }

    float w = d_wi[gw];
    float px, py;
    if (n >= 2) {
        float2 q = __half22float2(d_Ph[pb][(long)gw * (CC / 2) + lane]);
        px = 2.f * w * sx - q.x;
        py = 2.f * w * sy - q.y;
    } else {
        px = w * sx;
        py = w * sy;
    }

    int c2 = 2 * lane;
    float sd   = d_sdeg[gw];
    float coef = lap[n - 1];
    float w0 = coef * mfw[n * CC + c2];
    float w1 = coef * mfw[n * CC + c2 + 1];
    float2 a = *(const float2*)(d_acc + (long)gw * CC + c2);
    a.x += w0 * (sd * px);
    a.y += w1 * (sd * py);

    if (n < KORD) {
        d_Ph[outb][(long)gw * (CC / 2) + lane] = __floats2half2_rn(px, py);
        *(float2*)(d_acc + (long)gw * CC + c2) = a;
    } else {
        // fused log_softmax over the warp-held 64-wide row
        float m = fmaxf(a.x, a.y);
#pragma unroll
        for (int o = 16; o; o >>= 1) m = fmaxf(m, __shfl_xor_sync(0xffffffffu, m, o));
        float s = expf(a.x - m) + expf(a.y - m);
#pragma unroll
        for (int o = 16; o; o >>= 1) s += __shfl_xor_sync(0xffffffffu, s, o);
        float l = m + logf(s);
        *(float2*)(out + (long)gw * CC + c2) = make_float2(a.x - l, a.y - l);
    }
}

// ---------------- launch --------------------------------------------------------
extern "C" void kernel_launch(void* const* d_in, const int* in_sizes, int n_in,
                              void* d_out, int out_size) {
    const float* x   = (const float*)d_in[0];
    const int*   ei  = (const int*)d_in[1];     // int32 (JAX default x64-disabled)
    const float* W   = (const float*)d_in[2];
    const float* b   = (const float*)d_in[3];
    const float* lap = (const float*)d_in[4];
    const float* mfw = (const float*)d_in[5];
    float*       out = (float*)d_out;

    (void)in_sizes; (void)n_in; (void)out_size;

    // d_deg is zeroed (module load on call 1; k_scan3 re-zeroes every call)
    k_count<<<(EE + 255) / 256, 256>>>(ei);
    int nblk = (NN + 1023) / 1024;   // 98
    k_scan1<<<nblk, 1024>>>();
    k_scan2<<<1, 128>>>(nblk);
    k_scan3<<<(NN + 255) / 256, 256>>>();
    k_scatter<<<(EE + 255) / 256, 256>>>(ei);

    k_gemm<<<(NN + 127) / 128, 256>>>(x, W, b, mfw);

    // warps = NN, 8 warps/block
    int prop_blocks = (NN + 7) / 8;
    for (int n = 1; n <= KORD; n++) {
        int inb  = (n - 1) % 3;
        int outb = n % 3;
        int pb   = (n + 1) % 3;   // == (n-2) mod 3
        k_prop<<<prop_blocks, 256>>>(n, inb, outb, pb, lap, mfw, out);
    }
}